// round 1
// baseline (speedup 1.0000x reference)
#include <cuda_runtime.h>
#include <cuda_bf16.h>

// Problem constants
#define BATCH 256
#define TT    1024
#define INP   128
#define LAT   64
#define HID   128
#define OUTD  32

// Scratch: drive[b][t][l] (fp32), 256*1024*64 floats = 64 MB (static, allowed)
__device__ float g_drive[(size_t)BATCH * TT * LAT];

// ---------- f32x2 helpers ----------
__device__ __forceinline__ void fma2(unsigned long long& acc,
                                     unsigned long long a,
                                     unsigned long long b) {
    asm("fma.rn.f32x2 %0, %1, %2, %0;" : "+l"(acc) : "l"(a), "l"(b));
}
__device__ __forceinline__ float psum2(unsigned long long v) {
    float lo, hi;
    asm("mov.b64 {%0,%1}, %2;" : "=f"(lo), "=f"(hi) : "l"(v));
    return lo + hi;
}

// =====================================================================
// Kernel 1: drive = input @ C^T      [B*T,128] x [64,128]^T -> [B*T,64]
// Block: 256 threads, tile 128 rows x 64 cols, K=128 fully staged.
// Thread tile 8x4 with f32x2 packing over K.
// =====================================================================
__global__ void __launch_bounds__(256, 1)
drive_kernel(const float* __restrict__ inp, const float* __restrict__ Cg) {
    extern __shared__ char smem1[];
    float*  As = reinterpret_cast<float*>(smem1);                 // [128][132]
    float4* Cq = reinterpret_cast<float4*>(smem1 + 128 * 132 * 4); // [32][64]

    const int tid = threadIdx.x;
    const int m0  = blockIdx.x * 128;

    // stage input tile (128 rows x 128 k) as float4
    #pragma unroll
    for (int e = tid; e < 4096; e += 256) {
        int row = e >> 5;
        int c4  = e & 31;
        float4 v = reinterpret_cast<const float4*>(inp + (size_t)(m0 + row) * INP)[c4];
        *reinterpret_cast<float4*>(&As[row * 132 + c4 * 4]) = v;
    }
    // stage C packed by k-quads: Cq[jq][n] = (C[n][4jq..4jq+3])
    #pragma unroll
    for (int idx = tid; idx < 2048; idx += 256) {
        // idx = n*32 + jq
        Cq[(idx & 31) * 64 + (idx >> 5)] = reinterpret_cast<const float4*>(Cg)[idx];
    }
    __syncthreads();

    const int ctx = tid & 15;   // covers cols {ctx, ctx+16, ctx+32, ctx+48}
    const int rty = tid >> 4;   // covers rows rty*8 .. +7

    unsigned long long acc[8][4];
    #pragma unroll
    for (int r = 0; r < 8; ++r)
        #pragma unroll
        for (int c = 0; c < 4; ++c) acc[r][c] = 0ull;

    #pragma unroll 4
    for (int jq = 0; jq < 32; ++jq) {
        ulonglong2 cw[4];
        #pragma unroll
        for (int c = 0; c < 4; ++c)
            cw[c] = *reinterpret_cast<const ulonglong2*>(&Cq[jq * 64 + ctx + 16 * c]);
        #pragma unroll
        for (int r = 0; r < 8; ++r) {
            ulonglong2 av =
                *reinterpret_cast<const ulonglong2*>(&As[(rty * 8 + r) * 132 + 4 * jq]);
            #pragma unroll
            for (int c = 0; c < 4; ++c) {
                fma2(acc[r][c], av.x, cw[c].x);
                fma2(acc[r][c], av.y, cw[c].y);
            }
        }
    }

    #pragma unroll
    for (int r = 0; r < 8; ++r) {
        size_t row = (size_t)(m0 + rty * 8 + r);
        #pragma unroll
        for (int c = 0; c < 4; ++c)
            g_drive[row * LAT + ctx + 16 * c] = psum2(acc[r][c]);
    }
}

// =====================================================================
// Kernel 2: the scan. 128 blocks x 128 threads, 2 batches per block.
// Weights register-resident (W2 row per thread; half W1 row per thread).
// 2 barriers per step; f32x2 packed over reduction dims.
// =====================================================================
__global__ void __launch_bounds__(128, 1)
recur_kernel(const float* __restrict__ Ag,   const float* __restrict__ W1g,
             const float* __restrict__ W2g,  const float* __restrict__ h1g,
             const float* __restrict__ h2g,  const float* __restrict__ Woutg,
             const float* __restrict__ boutg, float* __restrict__ outg) {
    __shared__ __align__(16) float zs[2][LAT];
    __shared__ __align__(16) float hid0[HID];
    __shared__ __align__(16) float hid1[HID];
    __shared__ float As_[LAT], h1s[LAT], h2s[HID], bouts[OUTD];
    __shared__ float Wouts[OUTD * LAT];

    const int tid = threadIdx.x;
    const int b0  = blockIdx.x * 2;

    // register-resident weights
    // phase1: thread h=tid owns W2[h][0..63] as 32 packed pairs
    unsigned long long w2r[32];
    #pragma unroll
    for (int j = 0; j < 32; ++j)
        w2r[j] = *reinterpret_cast<const unsigned long long*>(&W2g[tid * LAT + 2 * j]);
    // phase2: thread (l2 = tid>>1, kp = tid&1) owns W1[l2][kp*64 .. +63]
    const int l2 = tid >> 1;
    const int kp = tid & 1;
    unsigned long long w1r[32];
    #pragma unroll
    for (int m = 0; m < 32; ++m)
        w1r[m] = *reinterpret_cast<const unsigned long long*>(
            &W1g[l2 * HID + kp * 64 + 2 * m]);

    if (tid < LAT) {
        As_[tid] = Ag[tid];
        h1s[tid] = h1g[tid];
        zs[0][tid] = 0.0f;
        zs[1][tid] = 0.0f;
    }
    h2s[tid] = h2g[tid];
    #pragma unroll
    for (int i = tid; i < OUTD * LAT; i += 128) Wouts[i] = Woutg[i];
    if (tid < OUTD) bouts[tid] = boutg[tid];
    __syncthreads();

    const float h2h = h2s[tid];
    const float Al  = As_[l2];
    const float h1l = h1s[l2];

    const int nb = kp; // batch owned in epilogue
    const size_t ubase = ((size_t)(b0 + nb)) * TT * LAT + l2;
    float u_cur = g_drive[ubase];
    float u_nxt = g_drive[ubase + LAT];

    for (int t = 0; t < TT; ++t) {
        float u_fut = (t < TT - 2) ? g_drive[ubase + (size_t)(t + 2) * LAT] : 0.0f;

        // ---- phase 1: hidden[nb][h=tid] = relu( z[nb] . W2[h] + h2[h] )
        unsigned long long a0 = 0, a1 = 0, c0 = 0, c1 = 0;
        #pragma unroll
        for (int jq = 0; jq < 16; ++jq) {
            ulonglong2 z0 = *reinterpret_cast<const ulonglong2*>(&zs[0][4 * jq]);
            ulonglong2 z1 = *reinterpret_cast<const ulonglong2*>(&zs[1][4 * jq]);
            fma2(a0, z0.x, w2r[2 * jq]);
            fma2(a1, z0.y, w2r[2 * jq + 1]);
            fma2(c0, z1.x, w2r[2 * jq]);
            fma2(c1, z1.y, w2r[2 * jq + 1]);
        }
        hid0[tid] = fmaxf(psum2(a0) + psum2(a1) + h2h, 0.0f);
        hid1[tid] = fmaxf(psum2(c0) + psum2(c1) + h2h, 0.0f);
        __syncthreads();

        // ---- phase 2: dot[nb][l2] = hidden[nb] . W1[l2]  (k-split over lane pair)
        unsigned long long p0a = 0, p0b = 0, p1a = 0, p1b = 0;
        #pragma unroll
        for (int jq = 0; jq < 16; ++jq) {
            const int fo = kp * 64 + 4 * jq;
            ulonglong2 H0 = *reinterpret_cast<const ulonglong2*>(&hid0[fo]);
            ulonglong2 H1 = *reinterpret_cast<const ulonglong2*>(&hid1[fo]);
            fma2(p0a, H0.x, w1r[2 * jq]);
            fma2(p0b, H0.y, w1r[2 * jq + 1]);
            fma2(p1a, H1.x, w1r[2 * jq]);
            fma2(p1b, H1.y, w1r[2 * jq + 1]);
        }
        float p0 = psum2(p0a) + psum2(p0b);
        float p1 = psum2(p1a) + psum2(p1b);
        p0 += __shfl_xor_sync(0xffffffffu, p0, 1);
        p1 += __shfl_xor_sync(0xffffffffu, p1, 1);
        const float dot = kp ? p1 : p0;

        float zn = zs[nb][l2] * Al + dot + h1l + u_cur;
        zn = fminf(5.0f, fmaxf(-5.0f, zn));
        zs[nb][l2] = zn;

        u_cur = u_nxt;
        u_nxt = u_fut;
        __syncthreads();
    }

    // ---- final: out[b0+onb][o] = zT . Wout[o] + bout[o]
    if (tid < 2 * OUTD) {
        const int onb = tid >> 5;
        const int o   = tid & 31;
        float acc = bouts[o];
        #pragma unroll
        for (int l = 0; l < LAT; ++l) acc += zs[onb][l] * Wouts[o * LAT + l];
        outg[(size_t)(b0 + onb) * OUTD + o] = acc;
    }
}

// =====================================================================
extern "C" void kernel_launch(void* const* d_in, const int* in_sizes, int n_in,
                              void* d_out, int out_size) {
    (void)in_sizes; (void)n_in; (void)out_size;
    const float* inp   = (const float*)d_in[0];
    const float* Ag    = (const float*)d_in[1];
    const float* W1g   = (const float*)d_in[2];
    const float* W2g   = (const float*)d_in[3];
    const float* h1g   = (const float*)d_in[4];
    const float* h2g   = (const float*)d_in[5];
    const float* Cg    = (const float*)d_in[6];
    const float* Woutg = (const float*)d_in[7];
    const float* boutg = (const float*)d_in[8];
    float* outg = (float*)d_out;

    const int smem1 = 128 * 132 * 4 + 32 * 64 * 16; // As + Cq = 100352 B
    cudaFuncSetAttribute(drive_kernel, cudaFuncAttributeMaxDynamicSharedMemorySize, smem1);

    drive_kernel<<<(BATCH * TT) / 128, 256, smem1>>>(inp, Cg);
    recur_kernel<<<BATCH / 2, 128>>>(Ag, W1g, W2g, h1g, h2g, Woutg, boutg, outg);
}

// round 2
// speedup vs baseline: 1.1785x; 1.1785x over previous
#include <cuda_runtime.h>
#include <cuda_bf16.h>

// Problem constants
#define BATCH 256
#define TT    1024
#define INP   128
#define LAT   64
#define HID   128
#define OUTD  32

// Scratch: drive[b][t][l] (fp32), 256*1024*64 floats = 64 MB
__device__ float g_drive[(size_t)BATCH * TT * LAT];

// ---------- f32x2 helpers ----------
__device__ __forceinline__ void fma2(unsigned long long& acc,
                                     unsigned long long a,
                                     unsigned long long b) {
    asm("fma.rn.f32x2 %0, %1, %2, %0;" : "+l"(acc) : "l"(a), "l"(b));
}
__device__ __forceinline__ float psum2(unsigned long long v) {
    float lo, hi;
    asm("mov.b64 {%0,%1}, %2;" : "=f"(lo), "=f"(hi) : "l"(v));
    return lo + hi;
}
__device__ __forceinline__ void gbar(int id) {
    asm volatile("bar.sync %0, 128;" :: "r"(id) : "memory");
}

// =====================================================================
// Kernel 1: drive = input @ C^T      [B*T,128] x [64,128]^T -> [B*T,64]
// =====================================================================
__global__ void __launch_bounds__(256, 1)
drive_kernel(const float* __restrict__ inp, const float* __restrict__ Cg) {
    extern __shared__ char smem1[];
    float*  As = reinterpret_cast<float*>(smem1);                 // [128][132]
    float4* Cq = reinterpret_cast<float4*>(smem1 + 128 * 132 * 4); // [32][64]

    const int tid = threadIdx.x;
    const int m0  = blockIdx.x * 128;

    #pragma unroll
    for (int e = tid; e < 4096; e += 256) {
        int row = e >> 5;
        int c4  = e & 31;
        float4 v = reinterpret_cast<const float4*>(inp + (size_t)(m0 + row) * INP)[c4];
        *reinterpret_cast<float4*>(&As[row * 132 + c4 * 4]) = v;
    }
    #pragma unroll
    for (int idx = tid; idx < 2048; idx += 256) {
        Cq[(idx & 31) * 64 + (idx >> 5)] = reinterpret_cast<const float4*>(Cg)[idx];
    }
    __syncthreads();

    const int ctx = tid & 15;
    const int rty = tid >> 4;

    unsigned long long acc[8][4];
    #pragma unroll
    for (int r = 0; r < 8; ++r)
        #pragma unroll
        for (int c = 0; c < 4; ++c) acc[r][c] = 0ull;

    #pragma unroll 4
    for (int jq = 0; jq < 32; ++jq) {
        ulonglong2 cw[4];
        #pragma unroll
        for (int c = 0; c < 4; ++c)
            cw[c] = *reinterpret_cast<const ulonglong2*>(&Cq[jq * 64 + ctx + 16 * c]);
        #pragma unroll
        for (int r = 0; r < 8; ++r) {
            ulonglong2 av =
                *reinterpret_cast<const ulonglong2*>(&As[(rty * 8 + r) * 132 + 4 * jq]);
            #pragma unroll
            for (int c = 0; c < 4; ++c) {
                fma2(acc[r][c], av.x, cw[c].x);
                fma2(acc[r][c], av.y, cw[c].y);
            }
        }
    }

    #pragma unroll
    for (int r = 0; r < 8; ++r) {
        size_t row = (size_t)(m0 + rty * 8 + r);
        #pragma unroll
        for (int c = 0; c < 4; ++c)
            g_drive[row * LAT + ctx + 16 * c] = psum2(acc[r][c]);
    }
}

// =====================================================================
// Kernel 2: the scan. 128 blocks x 256 threads. Two INDEPENDENT
// 128-thread groups per block (one batch each), synced by disjoint
// named barriers -> 2 decoupled dependency chains per SMSP.
// Weights register-resident. f32x2 packed over reduction dims.
// =====================================================================
__global__ void __launch_bounds__(256, 1)
recur_kernel(const float* __restrict__ Ag,   const float* __restrict__ W1g,
             const float* __restrict__ W2g,  const float* __restrict__ h1g,
             const float* __restrict__ h2g,  const float* __restrict__ Woutg,
             const float* __restrict__ boutg, float* __restrict__ outg) {
    __shared__ __align__(16) float zs[2][LAT];
    __shared__ __align__(16) float hid[2][HID];

    const int tid  = threadIdx.x;
    const int gid  = tid >> 7;        // group = batch within block
    const int wtid = tid & 127;       // thread within group
    const int bat  = blockIdx.x * 2 + gid;
    const int barid = 1 + gid;

    float* zsg  = zs[gid];
    float* hidg = hid[gid];

    // register-resident weights
    // phase1: thread wtid owns W2[wtid][0..63] as 32 packed pairs
    unsigned long long w2r[32];
    #pragma unroll
    for (int j = 0; j < 32; ++j)
        w2r[j] = *reinterpret_cast<const unsigned long long*>(&W2g[wtid * LAT + 2 * j]);
    // phase2: thread (l2 = wtid>>1, kp = wtid&1) owns W1[l2][kp*64 .. +63]
    const int l2 = wtid >> 1;
    const int kp = wtid & 1;
    unsigned long long w1r[32];
    #pragma unroll
    for (int m = 0; m < 32; ++m)
        w1r[m] = *reinterpret_cast<const unsigned long long*>(
            &W1g[l2 * HID + kp * 64 + 2 * m]);

    // per-thread constants straight from gmem (one-time)
    const float h2h = h2g[wtid];
    const float Al  = Ag[l2];
    const float h1l = h1g[l2];

    if (wtid < LAT) zsg[wtid] = 0.0f;
    __syncthreads();

    const size_t ubase = ((size_t)bat) * TT * LAT + l2;
    float u_cur = g_drive[ubase];
    float u_nxt = g_drive[ubase + LAT];

    for (int t = 0; t < TT; ++t) {
        float u_fut = (t < TT - 2) ? g_drive[ubase + (size_t)(t + 2) * LAT] : 0.0f;

        // ---- phase 1: hidden[wtid] = relu( z . W2[wtid] + h2 )
        unsigned long long a0 = 0, a1 = 0;
        #pragma unroll
        for (int jq = 0; jq < 16; ++jq) {
            ulonglong2 zv = *reinterpret_cast<const ulonglong2*>(&zsg[4 * jq]);
            fma2(a0, zv.x, w2r[2 * jq]);
            fma2(a1, zv.y, w2r[2 * jq + 1]);
        }
        hidg[wtid] = fmaxf(psum2(a0) + psum2(a1) + h2h, 0.0f);
        gbar(barid);

        // ---- phase 2: dot[l2] = hidden . W1[l2]  (k-split over lane pair)
        unsigned long long p0 = 0, p1 = 0;
        #pragma unroll
        for (int jq = 0; jq < 16; ++jq) {
            ulonglong2 hv = *reinterpret_cast<const ulonglong2*>(&hidg[kp * 64 + 4 * jq]);
            fma2(p0, hv.x, w1r[2 * jq]);
            fma2(p1, hv.y, w1r[2 * jq + 1]);
        }
        float p = psum2(p0) + psum2(p1);
        p += __shfl_xor_sync(0xffffffffu, p, 1);

        float zn = zsg[l2] * Al + p + h1l + u_cur;
        zn = fminf(5.0f, fmaxf(-5.0f, zn));
        zsg[l2] = zn;   // both kp lanes write the identical value

        u_cur = u_nxt;
        u_nxt = u_fut;
        gbar(barid);
    }

    // ---- final: out[bat][o] = zT . Wout[o] + bout[o]
    if (wtid < OUTD) {
        const int o = wtid;
        float acc = boutg[o];
        #pragma unroll
        for (int l = 0; l < LAT; ++l) acc += zsg[l] * Woutg[o * LAT + l];
        outg[(size_t)bat * OUTD + o] = acc;
    }
}

// =====================================================================
extern "C" void kernel_launch(void* const* d_in, const int* in_sizes, int n_in,
                              void* d_out, int out_size) {
    (void)in_sizes; (void)n_in; (void)out_size;
    const float* inp   = (const float*)d_in[0];
    const float* Ag    = (const float*)d_in[1];
    const float* W1g   = (const float*)d_in[2];
    const float* W2g   = (const float*)d_in[3];
    const float* h1g   = (const float*)d_in[4];
    const float* h2g   = (const float*)d_in[5];
    const float* Cg    = (const float*)d_in[6];
    const float* Woutg = (const float*)d_in[7];
    const float* boutg = (const float*)d_in[8];
    float* outg = (float*)d_out;

    const int smem1 = 128 * 132 * 4 + 32 * 64 * 16; // 100352 B
    cudaFuncSetAttribute(drive_kernel, cudaFuncAttributeMaxDynamicSharedMemorySize, smem1);

    drive_kernel<<<(BATCH * TT) / 128, 256, smem1>>>(inp, Cg);
    recur_kernel<<<BATCH / 2, 256>>>(Ag, W1g, W2g, h1g, h2g, Woutg, boutg, outg);
}